// round 9
// baseline (speedup 1.0000x reference)
#include <cuda_runtime.h>
#include <math.h>

#define H       2048
#define E       8
#define TPW     4               // tokens per warp
#define NWARPS  8
#define TPB     (TPW * NWARPS)  // 32 tokens per block
#define NTHR    256
#define NIT     16              // stages; each covers 128 floats of H per token
#define DEPTH   6               // ring depth
#define PF      5               // prefetch distance (stages ahead)
#define STG_B   (TPW * 512)     // 2048 B per warp-stage
#define RING_B  (DEPTH * STG_B) // 12288 B per warp
#define ALPHA   0.01f

__device__ float        g_acc[2 * E];   // [0..7] counts, [8..15] prob sums
__device__ unsigned int g_done = 0;

__device__ __forceinline__ void ffma2(unsigned long long& d,
                                      unsigned long long a,
                                      unsigned long long b)
{
    asm("fma.rn.f32x2 %0, %1, %2, %0;" : "+l"(d) : "l"(a), "l"(b));
}

__device__ __forceinline__ float pair_sum(unsigned long long p)
{
    float lo, hi;
    asm("mov.b64 {%0, %1}, %2;" : "=f"(lo), "=f"(hi) : "l"(p));
    return lo + hi;
}

__device__ __forceinline__ void cp16(unsigned int saddr, const void* gaddr)
{
    asm volatile("cp.async.cg.shared.global [%0], [%1], 16;"
                 :: "r"(saddr), "l"(gaddr));
}

__global__ __launch_bounds__(NTHR, 2)
void moe_gate_kernel(const float* __restrict__ x,
                     const float* __restrict__ w,
                     float* __restrict__ out_idx,
                     float* __restrict__ out_wgt,
                     float* __restrict__ out_aux,
                     int T)
{
    extern __shared__ char smem[];        // 8 warps x 12KB rings = 96KB
    __shared__ float s_cnt[E];
    __shared__ float s_psum[E];
    __shared__ unsigned int s_last;

    const int tid  = threadIdx.x;
    const int warp = tid >> 5;
    const int lane = tid & 31;
    const int tok0 = blockIdx.x * TPB + warp * TPW;

    const unsigned int ring_u32 =
        (unsigned int)__cvta_generic_to_shared(smem) + warp * RING_B + lane * 16;
    const char*  ring_gen = smem + warp * RING_B + lane * 16;
    const float* xg = x + (size_t)tok0 * H + lane * 4;

    auto issue_stage = [&](int s, int buf) {
        const unsigned int sb = ring_u32 + buf * STG_B;
        const float*       g  = xg + s * 128;
        #pragma unroll
        for (int t = 0; t < TPW; t++)
            cp16(sb + t * 512, g + (size_t)t * H);
        asm volatile("cp.async.commit_group;");
    };

    // prologue: PF stages in flight immediately (DRAM starts now)
    #pragma unroll
    for (int s = 0; s < PF; s++)
        issue_stage(s, s);

    if (tid < E)            s_cnt[tid] = 0.0f;
    else if (tid < 2 * E)   s_psum[tid - E] = 0.0f;
    __syncthreads();        // s_cnt/s_psum visible before any epilogue atomics

    unsigned long long acc2[TPW][E];
    #pragma unroll
    for (int t = 0; t < TPW; t++)
        #pragma unroll
        for (int e = 0; e < E; e++)
            acc2[t][e] = 0ull;

    const float* wl = w + lane * 4;       // weights straight from L1
    int buf_w = PF, buf_r = 0;

    for (int it = 0; it < NIT; it++) {
        if (it + PF < NIT) {
            issue_stage(it + PF, buf_w);
            if (++buf_w == DEPTH) buf_w = 0;
        } else {
            asm volatile("cp.async.commit_group;");   // keep group count uniform
        }
        asm volatile("cp.async.wait_group 5;");       // stage 'it' complete

        const char* xp = ring_gen + buf_r * STG_B;
        if (++buf_r == DEPTH) buf_r = 0;

        ulonglong2 xv[TPW];
        #pragma unroll
        for (int t = 0; t < TPW; t++)
            xv[t] = *reinterpret_cast<const ulonglong2*>(xp + t * 512);

        const float* wst = wl + it * 128;
        #pragma unroll
        for (int e = 0; e < E; e++) {
            const ulonglong2 wv =
                *reinterpret_cast<const ulonglong2*>(wst + (size_t)e * H);
            #pragma unroll
            for (int t = 0; t < TPW; t++) {
                ffma2(acc2[t][e], xv[t].x, wv.x);
                ffma2(acc2[t][e], xv[t].y, wv.y);
            }
        }
    }

    // unpack + warp tree-reduce
    float accf[TPW][E];
    #pragma unroll
    for (int t = 0; t < TPW; t++)
        #pragma unroll
        for (int e = 0; e < E; e++) {
            float v = pair_sum(acc2[t][e]);
            v += __shfl_xor_sync(0xffffffffu, v, 16);
            v += __shfl_xor_sync(0xffffffffu, v, 8);
            v += __shfl_xor_sync(0xffffffffu, v, 4);
            v += __shfl_xor_sync(0xffffffffu, v, 2);
            v += __shfl_xor_sync(0xffffffffu, v, 1);
            accf[t][e] = v;
        }

    if (lane < TPW) {
        const int tok = tok0 + lane;
        float lg[E];
        #pragma unroll
        for (int e = 0; e < E; e++) lg[e] = accf[lane][e];

        float m = lg[0];
        #pragma unroll
        for (int e = 1; e < E; e++) m = fmaxf(m, lg[e]);
        float p[E];
        float s = 0.0f;
        #pragma unroll
        for (int e = 0; e < E; e++) { p[e] = __expf(lg[e] - m); s += p[e]; }
        const float inv = 1.0f / s;

        int i1 = 0; float b1 = lg[0];
        #pragma unroll
        for (int e = 1; e < E; e++)
            if (lg[e] > b1) { b1 = lg[e]; i1 = e; }
        int i2 = -1; float b2 = -INFINITY;
        #pragma unroll
        for (int e = 0; e < E; e++)
            if (e != i1 && lg[e] > b2) { b2 = lg[e]; i2 = e; }

        out_idx[2 * tok]     = (float)i1;
        out_idx[2 * tok + 1] = (float)i2;
        out_wgt[2 * tok]     = p[i1] * inv;
        out_wgt[2 * tok + 1] = p[i2] * inv;

        atomicAdd(&s_cnt[i1], 1.0f);
        atomicAdd(&s_cnt[i2], 1.0f);
        #pragma unroll
        for (int e = 0; e < E; e++)
            atomicAdd(&s_psum[e], p[e] * inv);
    }

    __syncthreads();
    if (tid < E)           atomicAdd(&g_acc[tid], s_cnt[tid]);
    else if (tid < 2 * E)  atomicAdd(&g_acc[tid], s_psum[tid - E]);
    __threadfence();
    __syncthreads();

    // fused finalize: last block computes aux_loss and resets accumulators
    if (tid == 0)
        s_last = (atomicAdd(&g_done, 1u) == gridDim.x - 1) ? 1u : 0u;
    __syncthreads();

    if (s_last && tid == 0) {
        float aux = 0.0f;
        const float invT  = 1.0f / (float)T;
        const float invTK = 1.0f / ((float)T * 2.0f);
        #pragma unroll
        for (int e = 0; e < E; e++) {
            const float cnt  = atomicAdd(&g_acc[e], 0.0f);
            const float psum = atomicAdd(&g_acc[E + e], 0.0f);
            aux += (psum * invT) * (cnt * invTK * (float)E);
        }
        out_aux[0] = aux * ALPHA;
        #pragma unroll
        for (int i = 0; i < 2 * E; i++) {
            float old = atomicAdd(&g_acc[i], 0.0f);
            atomicAdd(&g_acc[i], -old);
        }
        atomicExch(&g_done, 0u);
    }
}

extern "C" void kernel_launch(void* const* d_in, const int* in_sizes, int n_in,
                              void* d_out, int out_size)
{
    const float* x = (const float*)d_in[0];   // [T, H]
    const float* w = (const float*)d_in[1];   // [E, H]
    const int T = in_sizes[0] / H;            // 16384

    float* out = (float*)d_out;
    float* out_idx = out;
    float* out_wgt = out + (size_t)T * 2;
    float* out_aux = out + (size_t)T * 4;

    const int smem_bytes = NWARPS * RING_B;   // 96KB rings
    cudaFuncSetAttribute(moe_gate_kernel,
                         cudaFuncAttributeMaxDynamicSharedMemorySize, smem_bytes);

    moe_gate_kernel<<<T / TPB, NTHR, smem_bytes>>>(x, w, out_idx, out_wgt, out_aux, T);
}

// round 10
// speedup vs baseline: 1.0356x; 1.0356x over previous
#include <cuda_runtime.h>
#include <math.h>

#define H       2048
#define E       8
#define TPW     4               // tokens per warp
#define NWARPS  8
#define TPB     (TPW * NWARPS)  // 32 tokens per block
#define NTHR    256
#define NIT     16              // stages; each covers 128 floats of H per token
#define DEPTH   6               // ring depth
#define PF      5               // prefetch distance (stages ahead)
#define STG_B   (TPW * 512)     // 2048 B per warp-stage
#define RING_B  (DEPTH * STG_B) // 12288 B per warp
#define ALPHA   0.01f

__device__ float        g_acc[2 * E];   // [0..7] counts, [8..15] prob sums
__device__ unsigned int g_done = 0;

__device__ __forceinline__ void ffma2(unsigned long long& d,
                                      unsigned long long a,
                                      unsigned long long b)
{
    asm("fma.rn.f32x2 %0, %1, %2, %0;" : "+l"(d) : "l"(a), "l"(b));
}

__device__ __forceinline__ float pair_sum(unsigned long long p)
{
    float lo, hi;
    asm("mov.b64 {%0, %1}, %2;" : "=f"(lo), "=f"(hi) : "l"(p));
    return lo + hi;
}

__device__ __forceinline__ void cp16(unsigned int saddr, const void* gaddr)
{
    asm volatile("cp.async.cg.shared.global [%0], [%1], 16;"
                 :: "r"(saddr), "l"(gaddr));
}

__global__ __launch_bounds__(NTHR, 2)
void moe_gate_kernel(const float* __restrict__ x,
                     const float* __restrict__ w,
                     float* __restrict__ out_idx,
                     float* __restrict__ out_wgt,
                     float* __restrict__ out_aux,
                     int T)
{
    extern __shared__ char smem[];        // 8 warps x 12KB rings = 96KB
    __shared__ float s_cnt[E];
    __shared__ float s_psum[E];
    __shared__ unsigned int s_last;

    const int tid  = threadIdx.x;
    const int warp = tid >> 5;
    const int lane = tid & 31;
    const int tok0 = blockIdx.x * TPB + warp * TPW;

    const unsigned int ring_u32 =
        (unsigned int)__cvta_generic_to_shared(smem) + warp * RING_B + lane * 16;
    const char*  ring_gen = smem + warp * RING_B + lane * 16;
    const float* xg = x + (size_t)tok0 * H + lane * 4;

    auto issue_stage = [&](int s, int buf) {
        const unsigned int sb = ring_u32 + buf * STG_B;
        const float*       g  = xg + s * 128;
        #pragma unroll
        for (int t = 0; t < TPW; t++)
            cp16(sb + t * 512, g + (size_t)t * H);
        asm volatile("cp.async.commit_group;");
    };

    // prologue: PF stages in flight immediately (DRAM starts now)
    #pragma unroll
    for (int s = 0; s < PF; s++)
        issue_stage(s, s);

    if (tid < E)            s_cnt[tid] = 0.0f;
    else if (tid < 2 * E)   s_psum[tid - E] = 0.0f;
    __syncthreads();        // s_cnt/s_psum visible before any epilogue atomics

    unsigned long long acc2[TPW][E];
    #pragma unroll
    for (int t = 0; t < TPW; t++)
        #pragma unroll
        for (int e = 0; e < E; e++)
            acc2[t][e] = 0ull;

    const float* wl = w + lane * 4;       // weights straight from L1
    int buf_w = PF, buf_r = 0;

    for (int it = 0; it < NIT; it++) {
        if (it + PF < NIT) {
            issue_stage(it + PF, buf_w);
            if (++buf_w == DEPTH) buf_w = 0;
        } else {
            asm volatile("cp.async.commit_group;");   // keep group count uniform
        }
        asm volatile("cp.async.wait_group 5;");       // stage 'it' complete

        const char* xp = ring_gen + buf_r * STG_B;
        if (++buf_r == DEPTH) buf_r = 0;

        ulonglong2 xv[TPW];
        #pragma unroll
        for (int t = 0; t < TPW; t++)
            xv[t] = *reinterpret_cast<const ulonglong2*>(xp + t * 512);

        const float* wst = wl + it * 128;
        #pragma unroll
        for (int e = 0; e < E; e++) {
            const ulonglong2 wv =
                *reinterpret_cast<const ulonglong2*>(wst + (size_t)e * H);
            #pragma unroll
            for (int t = 0; t < TPW; t++) {
                ffma2(acc2[t][e], xv[t].x, wv.x);
                ffma2(acc2[t][e], xv[t].y, wv.y);
            }
        }
    }

    // unpack + warp tree-reduce
    float accf[TPW][E];
    #pragma unroll
    for (int t = 0; t < TPW; t++)
        #pragma unroll
        for (int e = 0; e < E; e++) {
            float v = pair_sum(acc2[t][e]);
            v += __shfl_xor_sync(0xffffffffu, v, 16);
            v += __shfl_xor_sync(0xffffffffu, v, 8);
            v += __shfl_xor_sync(0xffffffffu, v, 4);
            v += __shfl_xor_sync(0xffffffffu, v, 2);
            v += __shfl_xor_sync(0xffffffffu, v, 1);
            accf[t][e] = v;
        }

    if (lane < TPW) {
        const int tok = tok0 + lane;
        float lg[E];
        #pragma unroll
        for (int e = 0; e < E; e++) lg[e] = accf[lane][e];

        float m = lg[0];
        #pragma unroll
        for (int e = 1; e < E; e++) m = fmaxf(m, lg[e]);
        float p[E];
        float s = 0.0f;
        #pragma unroll
        for (int e = 0; e < E; e++) { p[e] = __expf(lg[e] - m); s += p[e]; }
        const float inv = 1.0f / s;

        int i1 = 0; float b1 = lg[0];
        #pragma unroll
        for (int e = 1; e < E; e++)
            if (lg[e] > b1) { b1 = lg[e]; i1 = e; }
        int i2 = -1; float b2 = -INFINITY;
        #pragma unroll
        for (int e = 0; e < E; e++)
            if (e != i1 && lg[e] > b2) { b2 = lg[e]; i2 = e; }

        out_idx[2 * tok]     = (float)i1;
        out_idx[2 * tok + 1] = (float)i2;
        out_wgt[2 * tok]     = p[i1] * inv;
        out_wgt[2 * tok + 1] = p[i2] * inv;

        atomicAdd(&s_cnt[i1], 1.0f);
        atomicAdd(&s_cnt[i2], 1.0f);
        #pragma unroll
        for (int e = 0; e < E; e++)
            atomicAdd(&s_psum[e], p[e] * inv);
    }

    __syncthreads();
    if (tid < E)           atomicAdd(&g_acc[tid], s_cnt[tid]);
    else if (tid < 2 * E)  atomicAdd(&g_acc[tid], s_psum[tid - E]);
    __threadfence();
    __syncthreads();

    // fused finalize: last block computes aux_loss and resets accumulators
    if (tid == 0)
        s_last = (atomicAdd(&g_done, 1u) == gridDim.x - 1) ? 1u : 0u;
    __syncthreads();

    if (s_last && tid == 0) {
        float aux = 0.0f;
        const float invT  = 1.0f / (float)T;
        const float invTK = 1.0f / ((float)T * 2.0f);
        #pragma unroll
        for (int e = 0; e < E; e++) {
            const float cnt  = atomicAdd(&g_acc[e], 0.0f);
            const float psum = atomicAdd(&g_acc[E + e], 0.0f);
            aux += (psum * invT) * (cnt * invTK * (float)E);
        }
        out_aux[0] = aux * ALPHA;
        #pragma unroll
        for (int i = 0; i < 2 * E; i++) {
            float old = atomicAdd(&g_acc[i], 0.0f);
            atomicAdd(&g_acc[i], -old);
        }
        atomicExch(&g_done, 0u);
    }
}

extern "C" void kernel_launch(void* const* d_in, const int* in_sizes, int n_in,
                              void* d_out, int out_size)
{
    const float* x = (const float*)d_in[0];   // [T, H]
    const float* w = (const float*)d_in[1];   // [E, H]
    const int T = in_sizes[0] / H;            // 16384

    float* out = (float*)d_out;
    float* out_idx = out;
    float* out_wgt = out + (size_t)T * 2;
    float* out_aux = out + (size_t)T * 4;

    const int smem_bytes = NWARPS * RING_B;   // 96KB rings
    cudaFuncSetAttribute(moe_gate_kernel,
                         cudaFuncAttributeMaxDynamicSharedMemorySize, smem_bytes);

    moe_gate_kernel<<<T / TPB, NTHR, smem_bytes>>>(x, w, out_idx, out_wgt, out_aux, T);
}

// round 11
// speedup vs baseline: 1.3402x; 1.2941x over previous
#include <cuda_runtime.h>
#include <math.h>

#define H       2048
#define E       8
#define HV      (H / 4)        // 512 float4 per row
#define TPW     8              // tokens per warp
#define NWARPS  8
#define TPB     (TPW * NWARPS) // 64 tokens per block
#define NTHR    256
#define NIT     (HV / 32)      // 16 main-loop iterations
#define ALPHA   0.01f

// global accumulators: [0..7] = expert counts, [8..15] = sum of softmax probs
__device__ float        g_acc[2 * E];
__device__ unsigned int g_done = 0;

__global__ __launch_bounds__(NTHR, 2)
void moe_gate_kernel(const float* __restrict__ x,
                     const float* __restrict__ w,
                     float* __restrict__ out_idx,
                     float* __restrict__ out_wgt,
                     float* __restrict__ out_aux,
                     int T)
{
    extern __shared__ float smem[];               // E*H floats = 64KB
    __shared__ float s_cnt[E];
    __shared__ float s_psum[E];
    __shared__ unsigned int s_last;

    const int tid  = threadIdx.x;
    const int warp = tid >> 5;
    const int lane = tid & 31;

    if (tid < E)            s_cnt[tid] = 0.0f;
    else if (tid < 2 * E)   s_psum[tid - E] = 0.0f;

    // stage weight [E,H] into smem (16B vectors)
    {
        float4*       ws = reinterpret_cast<float4*>(smem);
        const float4* wg = reinterpret_cast<const float4*>(w);
        #pragma unroll
        for (int i = 0; i < (E * HV) / NTHR; i++)
            ws[tid + i * NTHR] = wg[tid + i * NTHR];
    }
    __syncthreads();

    const int tok0 = blockIdx.x * TPB + warp * TPW;
    const float4* x4 = reinterpret_cast<const float4*>(x) + (size_t)tok0 * HV + lane;
    const float4* w4 = reinterpret_cast<const float4*>(smem) + lane;

    float acc[TPW][E];
    #pragma unroll
    for (int t = 0; t < TPW; t++)
        #pragma unroll
        for (int e = 0; e < E; e++)
            acc[t][e] = 0.0f;

    #pragma unroll 1
    for (int it = 0; it < NIT; it++) {
        const int off = it * 32;
        // 8 independent streaming LDG.128 — front-batched, MLP=8
        float4 xv[TPW];
        #pragma unroll
        for (int t = 0; t < TPW; t++)
            xv[t] = __ldcs(&x4[(size_t)t * HV + off]);
        #pragma unroll
        for (int e = 0; e < E; e++) {
            const float4 wv = w4[e * HV + off];
            #pragma unroll
            for (int t = 0; t < TPW; t++) {
                acc[t][e] = fmaf(xv[t].x, wv.x, acc[t][e]);
                acc[t][e] = fmaf(xv[t].y, wv.y, acc[t][e]);
                acc[t][e] = fmaf(xv[t].z, wv.z, acc[t][e]);
                acc[t][e] = fmaf(xv[t].w, wv.w, acc[t][e]);
            }
        }
    }

    // warp tree-reduce (all lanes end with full sums)
    #pragma unroll
    for (int t = 0; t < TPW; t++)
        #pragma unroll
        for (int e = 0; e < E; e++) {
            float v = acc[t][e];
            v += __shfl_xor_sync(0xffffffffu, v, 16);
            v += __shfl_xor_sync(0xffffffffu, v, 8);
            v += __shfl_xor_sync(0xffffffffu, v, 4);
            v += __shfl_xor_sync(0xffffffffu, v, 2);
            v += __shfl_xor_sync(0xffffffffu, v, 1);
            acc[t][e] = v;
        }

    if (lane < TPW) {
        const int tok = tok0 + lane;
        float lg[E];
        #pragma unroll
        for (int e = 0; e < E; e++) lg[e] = acc[lane][e];

        // softmax
        float m = lg[0];
        #pragma unroll
        for (int e = 1; e < E; e++) m = fmaxf(m, lg[e]);
        float p[E];
        float s = 0.0f;
        #pragma unroll
        for (int e = 0; e < E; e++) { p[e] = __expf(lg[e] - m); s += p[e]; }
        const float inv = 1.0f / s;

        // top-2 on logits; ties -> lowest index first
        int i1 = 0; float b1 = lg[0];
        #pragma unroll
        for (int e = 1; e < E; e++)
            if (lg[e] > b1) { b1 = lg[e]; i1 = e; }
        int i2 = -1; float b2 = -INFINITY;
        #pragma unroll
        for (int e = 0; e < E; e++)
            if (e != i1 && lg[e] > b2) { b2 = lg[e]; i2 = e; }

        out_idx[2 * tok]     = (float)i1;
        out_idx[2 * tok + 1] = (float)i2;
        out_wgt[2 * tok]     = p[i1] * inv;
        out_wgt[2 * tok + 1] = p[i2] * inv;

        atomicAdd(&s_cnt[i1], 1.0f);
        atomicAdd(&s_cnt[i2], 1.0f);
        #pragma unroll
        for (int e = 0; e < E; e++)
            atomicAdd(&s_psum[e], p[e] * inv);
    }

    __syncthreads();
    if (tid < E)           atomicAdd(&g_acc[tid], s_cnt[tid]);
    else if (tid < 2 * E)  atomicAdd(&g_acc[tid], s_psum[tid - E]);
    __threadfence();
    __syncthreads();

    // fused finalize: last block computes aux_loss and resets accumulators
    if (tid == 0)
        s_last = (atomicAdd(&g_done, 1u) == gridDim.x - 1) ? 1u : 0u;
    __syncthreads();

    if (s_last && tid == 0) {
        float aux = 0.0f;
        const float invT  = 1.0f / (float)T;
        const float invTK = 1.0f / ((float)T * 2.0f);
        #pragma unroll
        for (int e = 0; e < E; e++) {
            const float cnt  = atomicAdd(&g_acc[e], 0.0f);
            const float psum = atomicAdd(&g_acc[E + e], 0.0f);
            aux += (psum * invT) * (cnt * invTK * (float)E);
        }
        out_aux[0] = aux * ALPHA;
        #pragma unroll
        for (int i = 0; i < 2 * E; i++) {
            float old = atomicAdd(&g_acc[i], 0.0f);
            atomicAdd(&g_acc[i], -old);
        }
        atomicExch(&g_done, 0u);
    }
}

extern "C" void kernel_launch(void* const* d_in, const int* in_sizes, int n_in,
                              void* d_out, int out_size)
{
    const float* x = (const float*)d_in[0];   // [T, H]
    const float* w = (const float*)d_in[1];   // [E, H]
    const int T = in_sizes[0] / H;            // 16384

    float* out = (float*)d_out;
    float* out_idx = out;
    float* out_wgt = out + (size_t)T * 2;
    float* out_aux = out + (size_t)T * 4;

    const int smem_bytes = E * H * (int)sizeof(float);   // 64KB
    cudaFuncSetAttribute(moe_gate_kernel,
                         cudaFuncAttributeMaxDynamicSharedMemorySize, smem_bytes);

    moe_gate_kernel<<<T / TPB, NTHR, smem_bytes>>>(x, w, out_idx, out_wgt, out_aux, T);
}